// round 15
// baseline (speedup 1.0000x reference)
#include <cuda_runtime.h>
#include <math.h>

#define NNODES 50000
#define NEDGES 800000
#define HID 128
#define NTYPES 4
#define YCOLS (NTYPES * HID)   /* 512 */
#define GCOLS (3 * HID)        /* 384 */

// ---------------- device scratch (no allocations allowed) ----------------
__device__ float g_Wcat[HID * YCOLS];                 // 128 x 512 concat of type_weights
__device__ float g_Y[(size_t)NNODES * YCOLS];         // h @ Wcat           (102.4 MB)
__device__ float g_msg[(size_t)NNODES * HID];         // aggregated messages (25.6 MB)
__device__ float g_S[(size_t)NNODES * GCOLS];         // messages @ gru_kernel + b0
__device__ float g_T[(size_t)NNODES * GCOLS];         // h @ gru_rec_kernel + b1
__device__ float g_H[(size_t)NNODES * HID];           // intermediate hidden state
// CSR build scratch (edges are fixed: built once per launch)
__device__ int g_deg[NNODES];
__device__ int g_off[NNODES + 1];
__device__ int g_cur[NNODES];
__device__ int g_sorted[NEDGES];                      // (src<<2)|etype, grouped by tgt

// ---- f32x2 packed-FMA helpers (sm_10x dual-fp32 pipe; PTX-only) ----
#define FMA2(d, a, b, c) \
    asm("fma.rn.f32x2 %0, %1, %2, %3;" : "=l"(d) : "l"(a), "l"(b), "l"(c))
#define DUP2(d, f) \
    asm("mov.b64 %0, {%1, %1};" : "=l"(d) : "f"(f))
#define UNPACK2(lo, hi, v) \
    asm("mov.b64 {%0, %1}, %2;" : "=f"(lo), "=f"(hi) : "l"(v))

// ---------------- prep: Wcat[k][t*128+j] = tw[t][k][j] ----------------
__global__ void prep_wcat(const float* __restrict__ tw) {
    int i = blockIdx.x * 256 + threadIdx.x;           // 65536 total
    int k = i >> 9;
    int c = i & 511;
    int t = c >> 7;
    int j = c & 127;
    g_Wcat[i] = tw[t * HID * HID + k * HID + j];
}

// ---------------- CSR build (once per launch) ----------------
__global__ void zero_deg_kernel() {
    int i = blockIdx.x * 256 + threadIdx.x;
    if (i < NNODES) g_deg[i] = 0;
}
__global__ void degree_kernel(const int* __restrict__ edges) {
    int e = blockIdx.x * 256 + threadIdx.x;           // exactly NEDGES
    atomicAdd(&g_deg[edges[e * 3 + 2]], 1);
}
// single-block exclusive scan over 50000 (1024 threads x 49-elem segments)
__global__ __launch_bounds__(1024) void scan_kernel() {
    __shared__ int part[1024];
    const int t = threadIdx.x;
    const int SEG = 49;                                // 1024*49 = 50176 >= 50000
    int start = t * SEG;
    int s = 0;
#pragma unroll 1
    for (int i = 0; i < SEG; i++) {
        int idx = start + i;
        if (idx < NNODES) s += g_deg[idx];
    }
    part[t] = s;
    __syncthreads();
    for (int d = 1; d < 1024; d <<= 1) {
        int v = (t >= d) ? part[t - d] : 0;
        __syncthreads();
        part[t] += v;
        __syncthreads();
    }
    int run = (t > 0) ? part[t - 1] : 0;
#pragma unroll 1
    for (int i = 0; i < SEG; i++) {
        int idx = start + i;
        if (idx < NNODES) {
            g_off[idx] = run;
            g_cur[idx] = run;
            run += g_deg[idx];
        }
    }
    if (t == 0) g_off[NNODES] = NEDGES;
}
__global__ void fill_kernel(const int* __restrict__ edges) {
    int e = blockIdx.x * 256 + threadIdx.x;           // exactly NEDGES
    int et  = edges[e * 3 + 0];
    int src = edges[e * 3 + 1];
    int tgt = edges[e * 3 + 2];
    int pos = atomicAdd(&g_cur[tgt], 1);
    g_sorted[pos] = (src << 2) | et;
}

// ---------------- SGEMM: C[M,N] = A[M,128] @ B[128,N] (+ bias row) ----------------
// 128x128 tile, 256 threads, 8m x 8n microtile, K in 32-chunks, double-buffered
// smem with register staging (LDG of next chunk overlaps FFMA2 of current).
// A tile stored transposed [k][m] (stride 132) so LDS128 yields packed m-pairs
// for fma.rn.f32x2; B scalars are dup'd. One __syncthreads per chunk.
#define TSTRIDE 132
#define ACHUNK  (32 * TSTRIDE)       /* floats per A stage */
#define STAGE   (2 * ACHUNK)         /* A + B per stage    */
__global__ __launch_bounds__(256) void sgemm128(
    const float* __restrict__ A, const float* __restrict__ B,
    float* __restrict__ C, int M, int N, const float* __restrict__ bias)
{
    extern __shared__ float sm[];

    const int bm = blockIdx.y << 7;   // 128 rows
    const int bn = blockIdx.x << 7;   // 128 cols (N is a multiple of 128)
    const int tid = threadIdx.x;
    const int tx = tid & 15, ty = tid >> 4;
    const int m0 = ty << 3;           // 8 rows / thread
    const int n0 = tx << 3;           // 8 cols / thread

    // staging thread mapping
    const int ar  = tid >> 3;         // +it*32 -> tile row 0..127
    const int akq = (tid & 7) << 2;   // k offset 0..28
    const int bk  = tid >> 5;         // +it*8  -> k 0..31
    const int bc  = (tid & 31) << 2;  // n offset 0..124

    unsigned long long acc[4][8];     // [m-pair][n]
#pragma unroll
    for (int p = 0; p < 4; p++)
#pragma unroll
        for (int j = 0; j < 8; j++) acc[p][j] = 0ull;

    float4 ra[4], rb[4];

    // ---- prologue: load chunk 0 ----
#pragma unroll
    for (int it = 0; it < 4; it++) {
        int row = bm + ar + it * 32;
        ra[it] = (row < M) ? *(const float4*)(A + (size_t)row * HID + akq)
                           : make_float4(0.f, 0.f, 0.f, 0.f);
        rb[it] = *(const float4*)(B + (size_t)(bk + it * 8) * N + bn + bc);
    }
    {
        float* dA = sm;
        float* dB = sm + ACHUNK;
#pragma unroll
        for (int it = 0; it < 4; it++) {
            int r = ar + it * 32;
            dA[(akq + 0) * TSTRIDE + r] = ra[it].x;
            dA[(akq + 1) * TSTRIDE + r] = ra[it].y;
            dA[(akq + 2) * TSTRIDE + r] = ra[it].z;
            dA[(akq + 3) * TSTRIDE + r] = ra[it].w;
            *(float4*)(dB + (bk + it * 8) * TSTRIDE + bc) = rb[it];
        }
    }
    __syncthreads();

    for (int c = 0; c < 4; c++) {
        // issue LDG for next chunk (latency hidden under compute)
        if (c < 3) {
            int kk = (c + 1) * 32;
#pragma unroll
            for (int it = 0; it < 4; it++) {
                int row = bm + ar + it * 32;
                ra[it] = (row < M) ? *(const float4*)(A + (size_t)row * HID + kk + akq)
                                   : make_float4(0.f, 0.f, 0.f, 0.f);
                rb[it] = *(const float4*)(B + (size_t)(kk + bk + it * 8) * N + bn + bc);
            }
        }
        // compute current chunk
        {
            const float* sA = sm + (c & 1) * STAGE;
            const float* sB = sA + ACHUNK;
#pragma unroll
            for (int k = 0; k < 32; k++) {
                ulonglong2 aA = *(const ulonglong2*)(sA + k * TSTRIDE + m0);
                ulonglong2 aB = *(const ulonglong2*)(sA + k * TSTRIDE + m0 + 4);
                float4 b1 = *(const float4*)(sB + k * TSTRIDE + n0);
                float4 b2 = *(const float4*)(sB + k * TSTRIDE + n0 + 4);
                unsigned long long d0, d1, d2, d3, d4, d5, d6, d7;
                DUP2(d0, b1.x); DUP2(d1, b1.y); DUP2(d2, b1.z); DUP2(d3, b1.w);
                DUP2(d4, b2.x); DUP2(d5, b2.y); DUP2(d6, b2.z); DUP2(d7, b2.w);
                FMA2(acc[0][0], aA.x, d0, acc[0][0]);
                FMA2(acc[0][1], aA.x, d1, acc[0][1]);
                FMA2(acc[0][2], aA.x, d2, acc[0][2]);
                FMA2(acc[0][3], aA.x, d3, acc[0][3]);
                FMA2(acc[0][4], aA.x, d4, acc[0][4]);
                FMA2(acc[0][5], aA.x, d5, acc[0][5]);
                FMA2(acc[0][6], aA.x, d6, acc[0][6]);
                FMA2(acc[0][7], aA.x, d7, acc[0][7]);
                FMA2(acc[1][0], aA.y, d0, acc[1][0]);
                FMA2(acc[1][1], aA.y, d1, acc[1][1]);
                FMA2(acc[1][2], aA.y, d2, acc[1][2]);
                FMA2(acc[1][3], aA.y, d3, acc[1][3]);
                FMA2(acc[1][4], aA.y, d4, acc[1][4]);
                FMA2(acc[1][5], aA.y, d5, acc[1][5]);
                FMA2(acc[1][6], aA.y, d6, acc[1][6]);
                FMA2(acc[1][7], aA.y, d7, acc[1][7]);
                FMA2(acc[2][0], aB.x, d0, acc[2][0]);
                FMA2(acc[2][1], aB.x, d1, acc[2][1]);
                FMA2(acc[2][2], aB.x, d2, acc[2][2]);
                FMA2(acc[2][3], aB.x, d3, acc[2][3]);
                FMA2(acc[2][4], aB.x, d4, acc[2][4]);
                FMA2(acc[2][5], aB.x, d5, acc[2][5]);
                FMA2(acc[2][6], aB.x, d6, acc[2][6]);
                FMA2(acc[2][7], aB.x, d7, acc[2][7]);
                FMA2(acc[3][0], aB.y, d0, acc[3][0]);
                FMA2(acc[3][1], aB.y, d1, acc[3][1]);
                FMA2(acc[3][2], aB.y, d2, acc[3][2]);
                FMA2(acc[3][3], aB.y, d3, acc[3][3]);
                FMA2(acc[3][4], aB.y, d4, acc[3][4]);
                FMA2(acc[3][5], aB.y, d5, acc[3][5]);
                FMA2(acc[3][6], aB.y, d6, acc[3][6]);
                FMA2(acc[3][7], aB.y, d7, acc[3][7]);
            }
        }
        // store next chunk into the other stage
        if (c < 3) {
            float* dA = sm + ((c + 1) & 1) * STAGE;
            float* dB = dA + ACHUNK;
#pragma unroll
            for (int it = 0; it < 4; it++) {
                int r = ar + it * 32;
                dA[(akq + 0) * TSTRIDE + r] = ra[it].x;
                dA[(akq + 1) * TSTRIDE + r] = ra[it].y;
                dA[(akq + 2) * TSTRIDE + r] = ra[it].z;
                dA[(akq + 3) * TSTRIDE + r] = ra[it].w;
                *(float4*)(dB + (bk + it * 8) * TSTRIDE + bc) = rb[it];
            }
        }
        __syncthreads();
    }

    // ---- epilogue ----
    float bs[8];
#pragma unroll
    for (int j = 0; j < 8; j++) bs[j] = bias ? bias[bn + n0 + j] : 0.f;

#pragma unroll
    for (int p = 0; p < 4; p++) {
        float lo[8], hi[8];
#pragma unroll
        for (int j = 0; j < 8; j++) UNPACK2(lo[j], hi[j], acc[p][j]);
        int r0 = bm + m0 + (p << 1);
        if (r0 < M) {
            float* o = C + (size_t)r0 * N + bn + n0;
            *(float4*)(o)     = make_float4(lo[0] + bs[0], lo[1] + bs[1], lo[2] + bs[2], lo[3] + bs[3]);
            *(float4*)(o + 4) = make_float4(lo[4] + bs[4], lo[5] + bs[5], lo[6] + bs[6], lo[7] + bs[7]);
        }
        if (r0 + 1 < M) {
            float* o = C + (size_t)(r0 + 1) * N + bn + n0;
            *(float4*)(o)     = make_float4(hi[0] + bs[0], hi[1] + bs[1], hi[2] + bs[2], hi[3] + bs[3]);
            *(float4*)(o + 4) = make_float4(hi[4] + bs[4], hi[5] + bs[5], hi[6] + bs[6], hi[7] + bs[7]);
        }
    }
}

// ---------------- gather: msg[n] = sum_{e: tgt=n} Y[src_e, etype_e] + counts@tb ----------------
// Warp per node over the CSR list: no atomics, no zero pass, bias folded in.
__global__ __launch_bounds__(256) void gather_kernel(const float* __restrict__ tb) {
    int w = (blockIdx.x * 256 + threadIdx.x) >> 5;    // node id, exactly NNODES
    int lane = threadIdx.x & 31;
    if (w >= NNODES) return;
    int beg = g_off[w], end = g_off[w + 1];
    float4 acc = make_float4(0.f, 0.f, 0.f, 0.f);
    int c0 = 0, c1 = 0, c2 = 0, c3 = 0;
    for (int e = beg; e < end; e++) {
        int pk = __ldg(&g_sorted[e]);
        int src = pk >> 2, et = pk & 3;
        float4 v = __ldg((const float4*)(g_Y + (size_t)src * YCOLS + et * HID + (lane << 2)));
        acc.x += v.x; acc.y += v.y; acc.z += v.z; acc.w += v.w;
        c0 += (et == 0); c1 += (et == 1); c2 += (et == 2); c3 += (et == 3);
    }
    const float4 b0 = __ldg((const float4*)(tb + 0 * HID + (lane << 2)));
    const float4 b1 = __ldg((const float4*)(tb + 1 * HID + (lane << 2)));
    const float4 b2 = __ldg((const float4*)(tb + 2 * HID + (lane << 2)));
    const float4 b3 = __ldg((const float4*)(tb + 3 * HID + (lane << 2)));
    float f0 = (float)c0, f1 = (float)c1, f2 = (float)c2, f3 = (float)c3;
    acc.x += f0 * b0.x + f1 * b1.x + f2 * b2.x + f3 * b3.x;
    acc.y += f0 * b0.y + f1 * b1.y + f2 * b2.y + f3 * b3.y;
    acc.z += f0 * b0.z + f1 * b1.z + f2 * b2.z + f3 * b3.z;
    acc.w += f0 * b0.w + f1 * b1.w + f2 * b2.w + f3 * b3.w;
    *(float4*)(g_msg + (size_t)w * HID + (lane << 2)) = acc;
}

// ---------------- GRU elementwise ----------------
__global__ void gru_kernel(const float* __restrict__ h_in, float* __restrict__ h_out) {
    int i = blockIdx.x * 256 + threadIdx.x;           // exactly NNODES*HID
    int n = i >> 7, j = i & 127;
    size_t b = (size_t)n * GCOLS;
    float xz = g_S[b + j], xr = g_S[b + HID + j], xh = g_S[b + 2 * HID + j];
    float rz = g_T[b + j], rr = g_T[b + HID + j], rh = g_T[b + 2 * HID + j];
    float z  = 1.f / (1.f + expf(-(xz + rz)));
    float r  = 1.f / (1.f + expf(-(xr + rr)));
    float hh = tanhf(xh + r * rh);
    float h  = h_in[i];
    h_out[i] = z * h + (1.f - z) * hh;
}

// ---------------- launch ----------------
extern "C" void kernel_launch(void* const* d_in, const int* in_sizes, int n_in,
                              void* d_out, int out_size) {
    const float* states = (const float*)d_in[0];   // (50000,128)
    const int*   edges  = (const int*)d_in[1];     // (800000,3) [etype,src,tgt]
    const float* tw     = (const float*)d_in[2];   // (4,128,128)
    const float* tb     = (const float*)d_in[3];   // (4,128)
    const float* gk     = (const float*)d_in[4];   // (128,384)
    const float* grk    = (const float*)d_in[5];   // (128,384)
    const float* gb     = (const float*)d_in[6];   // (2,384)
    float* out = (float*)d_out;

    float *pWcat, *pY, *pMsg, *pS, *pT, *pH;
    cudaGetSymbolAddress((void**)&pWcat, g_Wcat);
    cudaGetSymbolAddress((void**)&pY,    g_Y);
    cudaGetSymbolAddress((void**)&pMsg,  g_msg);
    cudaGetSymbolAddress((void**)&pS,    g_S);
    cudaGetSymbolAddress((void**)&pT,    g_T);
    cudaGetSymbolAddress((void**)&pH,    g_H);

    const int smem = 2 * STAGE * (int)sizeof(float);   // 67,584 B
    static bool attr_set = false;
    cudaFuncSetAttribute(sgemm128, cudaFuncAttributeMaxDynamicSharedMemorySize, smem);
    (void)attr_set;

    prep_wcat<<<256, 256>>>(tw);

    // CSR build (edges fixed for both steps)
    zero_deg_kernel<<<196, 256>>>();
    degree_kernel<<<NEDGES / 256, 256>>>(edges);
    scan_kernel<<<1, 1024>>>();
    fill_kernel<<<NEDGES / 256, 256>>>(edges);

    const int mblocks = (NNODES + 127) / 128;   // 391

    const float* h_in = states;
    float* h_out = pH;
    for (int step = 0; step < 2; step++) {
        // Y = h @ Wcat   (M=50000, N=512, K=128)
        sgemm128<<<dim3(4, mblocks), 256, smem>>>(h_in, pWcat, pY, NNODES, YCOLS, nullptr);
        // messages = segment_sum over CSR (+ per-type bias counts)
        gather_kernel<<<6250, 256>>>(tb);
        // S = messages @ gru_kernel + gb[0];  T = h @ gru_rec_kernel + gb[1]
        sgemm128<<<dim3(3, mblocks), 256, smem>>>(pMsg, gk,  pS, NNODES, GCOLS, gb);
        sgemm128<<<dim3(3, mblocks), 256, smem>>>(h_in, grk, pT, NNODES, GCOLS, gb + GCOLS);
        // h = GRU(messages, h)
        gru_kernel<<<25000, 256>>>(h_in, h_out);

        h_in = pH;
        h_out = out;   // step 1 writes final output
    }
}